// round 1
// baseline (speedup 1.0000x reference)
#include <cuda_runtime.h>
#include <cuda_bf16.h>
#include <stdint.h>

#define NN 50000
#define EE 800000
#define HH 128
#define CC 10
#define LL 3
#define OO 2
#define KHOP 10
#define GG 128

// ---------------- scratch (static device arrays; no allocation) ----------------
__device__ float g_zA[(size_t)NN * HH];
__device__ float g_zB[(size_t)NN * HH];
__device__ float g_xcat[(size_t)NN * (OO * HH)];   // concat of per-order hid
__device__ float g_xc[(size_t)NN * HH];
__device__ float g_h[(size_t)NN * HH];
__device__ int   g_rowptr[OO * (NN + 1)];
__device__ int   g_cursor[OO * NN];                // also reused as counts
__device__ int   g_csrc[OO * EE];
__device__ float g_cw[OO * EE];
__device__ float g_pool[GG * HH];
__device__ float g_p1[GG * HH];

// ---------------- CSR build ----------------
__global__ void csr_count(const int* __restrict__ dst, int* __restrict__ cnt) {
    int e = blockIdx.x * blockDim.x + threadIdx.x;
    if (e < EE) atomicAdd(&cnt[dst[e]], 1);
}

__global__ void csr_scan(const int* __restrict__ cnt, int* __restrict__ rowptr) {
    __shared__ int sdata[1024];
    __shared__ int sbase;
    int t = threadIdx.x;
    if (t == 0) { rowptr[0] = 0; sbase = 0; }
    __syncthreads();
    for (int c = 0; c < NN; c += 1024) {
        int v = (c + t < NN) ? cnt[c + t] : 0;
        sdata[t] = v;
        __syncthreads();
        for (int off = 1; off < 1024; off <<= 1) {
            int add = (t >= off) ? sdata[t - off] : 0;
            __syncthreads();
            sdata[t] += add;
            __syncthreads();
        }
        if (c + t < NN) rowptr[c + t + 1] = sbase + sdata[t];
        __syncthreads();
        if (t == 0) sbase += sdata[1023];
        __syncthreads();
    }
}

__global__ void csr_fill(const int* __restrict__ dst, const int* __restrict__ src,
                         const float* __restrict__ w,
                         int* __restrict__ cursor,
                         int* __restrict__ csrc, float* __restrict__ cw) {
    int e = blockIdx.x * blockDim.x + threadIdx.x;
    if (e < EE) {
        int pos = atomicAdd(&cursor[dst[e]], 1);
        csrc[pos] = src[e];
        cw[pos]   = w[e];
    }
}

// ---------------- fused SGEMM: out[N,128] = A[N,K] @ B[K,128] (+bias, +bn/relu, +hid seed) ----------------
__global__ __launch_bounds__(256) void gemm_fused(
    const float* __restrict__ A, int K,
    const float* __restrict__ B,
    const float* __restrict__ bias,
    float* __restrict__ out,
    float* __restrict__ hid,                // if non-null: hid[row*256+c] = fw0 * out
    const float* __restrict__ fw0p,
    const float* __restrict__ gam,          // if non-null: out = relu((acc+bias)*gam*RS + bet)
    const float* __restrict__ bet)
{
    __shared__ float As[8][128];
    __shared__ float Bs[8][128];
    const int tid = threadIdx.x;
    const int tx = tid & 15;
    const int ty = tid >> 4;
    const int rowBase = blockIdx.x * 128;

    float acc[8][8];
#pragma unroll
    for (int i = 0; i < 8; i++)
#pragma unroll
        for (int j = 0; j < 8; j++) acc[i][j] = 0.f;

    const int ar = tid >> 1;
    const int ac = (tid & 1) * 4;
    const int br = tid >> 5;
    const int bc = (tid & 31) * 4;
    const int arow = rowBase + ar;
    const bool avalid = (arow < NN);
    const float* Aptr = A + (size_t)arow * K + ac;
    const float* Bptr = B + (size_t)br * 128 + bc;

    for (int k0 = 0; k0 < K; k0 += 8) {
        float4 av = avalid ? *(const float4*)(Aptr + k0) : make_float4(0.f, 0.f, 0.f, 0.f);
        float4 bv = *(const float4*)(Bptr + (size_t)k0 * 128);
        As[ac + 0][ar] = av.x; As[ac + 1][ar] = av.y;
        As[ac + 2][ar] = av.z; As[ac + 3][ar] = av.w;
        *(float4*)&Bs[br][bc] = bv;
        __syncthreads();
#pragma unroll
        for (int k = 0; k < 8; k++) {
            float a[8], b[8];
            *(float4*)&a[0] = *(const float4*)&As[k][ty * 4];
            *(float4*)&a[4] = *(const float4*)&As[k][64 + ty * 4];
            *(float4*)&b[0] = *(const float4*)&Bs[k][tx * 4];
            *(float4*)&b[4] = *(const float4*)&Bs[k][64 + tx * 4];
#pragma unroll
            for (int i = 0; i < 8; i++)
#pragma unroll
                for (int j = 0; j < 8; j++)
                    acc[i][j] = fmaf(a[i], b[j], acc[i][j]);
        }
        __syncthreads();
    }

    const float RS = 0.9999950000374997f;  // 1/sqrt(1 + 1e-5)
    const float fw0 = (hid != nullptr) ? fw0p[0] : 0.f;

#pragma unroll
    for (int i = 0; i < 8; i++) {
        int r = (i < 4) ? (ty * 4 + i) : (64 + ty * 4 + (i - 4));
        int grow = rowBase + r;
        if (grow >= NN) continue;
#pragma unroll
        for (int jh = 0; jh < 2; jh++) {
            int cbase = jh * 64 + tx * 4;
            float4 v;
            float* vp = &v.x;
#pragma unroll
            for (int j = 0; j < 4; j++) {
                int c = cbase + j;
                float t = acc[i][jh * 4 + j] + bias[c];
                if (gam) t = fmaxf(t * gam[c] * RS + bet[c], 0.f);
                vp[j] = t;
            }
            *(float4*)(out + (size_t)grow * 128 + cbase) = v;
            if (hid) {
                float4 hv = make_float4(fw0 * v.x, fw0 * v.y, fw0 * v.z, fw0 * v.w);
                *(float4*)(hid + (size_t)grow * 256 + cbase) = hv;
            }
        }
    }
}

// ---------------- SpMM hop: zout[i] = sum_e w*zin[src]; hid[i] += fw * zout[i] ----------------
__global__ __launch_bounds__(256) void spmm_hop(
    const int* __restrict__ rowptr,
    const int* __restrict__ csrc,
    const float* __restrict__ cw,
    const float* __restrict__ zin,
    float* __restrict__ zout,
    float* __restrict__ hid,        // pre-offset by order, row stride 256
    const float* __restrict__ fwp)
{
    int warp = (blockIdx.x * blockDim.x + threadIdx.x) >> 5;
    int lane = threadIdx.x & 31;
    if (warp >= NN) return;
    int beg = rowptr[warp], end = rowptr[warp + 1];

    float ax = 0.f, ay = 0.f, az = 0.f, aw = 0.f;
    int e = beg;
    for (; e + 4 <= end; e += 4) {
        int s0 = csrc[e], s1 = csrc[e + 1], s2 = csrc[e + 2], s3 = csrc[e + 3];
        float w0 = cw[e], w1 = cw[e + 1], w2 = cw[e + 2], w3 = cw[e + 3];
        float4 v0 = *(const float4*)(zin + (size_t)s0 * 128 + lane * 4);
        float4 v1 = *(const float4*)(zin + (size_t)s1 * 128 + lane * 4);
        float4 v2 = *(const float4*)(zin + (size_t)s2 * 128 + lane * 4);
        float4 v3 = *(const float4*)(zin + (size_t)s3 * 128 + lane * 4);
        ax = fmaf(w0, v0.x, fmaf(w1, v1.x, fmaf(w2, v2.x, fmaf(w3, v3.x, ax))));
        ay = fmaf(w0, v0.y, fmaf(w1, v1.y, fmaf(w2, v2.y, fmaf(w3, v3.y, ay))));
        az = fmaf(w0, v0.z, fmaf(w1, v1.z, fmaf(w2, v2.z, fmaf(w3, v3.z, az))));
        aw = fmaf(w0, v0.w, fmaf(w1, v1.w, fmaf(w2, v2.w, fmaf(w3, v3.w, aw))));
    }
    for (; e < end; ++e) {
        int s = csrc[e];
        float w = cw[e];
        float4 v = *(const float4*)(zin + (size_t)s * 128 + lane * 4);
        ax = fmaf(w, v.x, ax); ay = fmaf(w, v.y, ay);
        az = fmaf(w, v.z, az); aw = fmaf(w, v.w, aw);
    }

    size_t zo = (size_t)warp * 128 + lane * 4;
    *(float4*)(zout + zo) = make_float4(ax, ay, az, aw);

    float fw = fwp[0];
    size_t ho = (size_t)warp * 256 + lane * 4;
    float4 hv = *(float4*)(hid + ho);
    hv.x = fmaf(fw, ax, hv.x); hv.y = fmaf(fw, ay, hv.y);
    hv.z = fmaf(fw, az, hv.z); hv.w = fmaf(fw, aw, hv.w);
    *(float4*)(hid + ho) = hv;
}

// ---------------- pooling + head ----------------
__global__ void pool_kernel(const float* __restrict__ h, const int* __restrict__ batch,
                            float* __restrict__ p) {
    int idx = blockIdx.x * blockDim.x + threadIdx.x;
    if (idx >= NN * HH) return;
    int node = idx >> 7;
    int f = idx & 127;
    atomicAdd(&p[batch[node] * HH + f], h[idx]);
}

__global__ void head1(const float* __restrict__ p, const float* __restrict__ W1,
                      const float* __restrict__ b1, float* __restrict__ p1) {
    int i = blockIdx.x * blockDim.x + threadIdx.x;
    if (i >= GG * HH) return;
    int g = i >> 7, j = i & 127;
    float acc = b1[j];
    for (int k = 0; k < HH; k++)
        acc = fmaf(p[g * HH + k], W1[k * HH + j], acc);
    p1[i] = fmaxf(acc, 0.f);
}

__global__ void head2(const float* __restrict__ p1, const float* __restrict__ W2,
                      const float* __restrict__ b2, float* __restrict__ outp) {
    int i = blockIdx.x * blockDim.x + threadIdx.x;
    if (i >= GG * CC) return;
    int g = i / CC, j = i % CC;
    float acc = b2[j];
    for (int k = 0; k < HH; k++)
        acc = fmaf(p1[g * HH + k], W2[k * CC + j], acc);
    outp[i] = acc;
}

// ---------------- host orchestration ----------------
extern "C" void kernel_launch(void* const* d_in, const int* in_sizes, int n_in,
                              void* d_out, int out_size) {
    const float* x      = (const float*)d_in[0];
    const int*   eidx   = (const int*)  d_in[1];
    const float* ew     = (const float*)d_in[2];
    const int*   batch  = (const int*)  d_in[3];
    const float* W_in   = (const float*)d_in[4];
    const float* b_in   = (const float*)d_in[5];
    const float* fW     = (const float*)d_in[6];
    const float* W_out  = (const float*)d_in[7];
    const float* b_out  = (const float*)d_in[8];
    const float* Wn1    = (const float*)d_in[9];
    const float* bn1    = (const float*)d_in[10];
    const float* g1     = (const float*)d_in[11];
    const float* be1    = (const float*)d_in[12];
    const float* Wn2    = (const float*)d_in[13];
    const float* bn2    = (const float*)d_in[14];
    const float* g2     = (const float*)d_in[15];
    const float* be2    = (const float*)d_in[16];
    const float* W1     = (const float*)d_in[17];
    const float* b1     = (const float*)d_in[18];
    const float* W2     = (const float*)d_in[19];
    const float* b2     = (const float*)d_in[20];
    float* outp = (float*)d_out;

    float *zA, *zB, *xcat, *xc, *hbuf, *pool, *p1, *cw;
    int *rowptr, *cursor, *csrc;
    cudaGetSymbolAddress((void**)&zA, g_zA);
    cudaGetSymbolAddress((void**)&zB, g_zB);
    cudaGetSymbolAddress((void**)&xcat, g_xcat);
    cudaGetSymbolAddress((void**)&xc, g_xc);
    cudaGetSymbolAddress((void**)&hbuf, g_h);
    cudaGetSymbolAddress((void**)&pool, g_pool);
    cudaGetSymbolAddress((void**)&p1, g_p1);
    cudaGetSymbolAddress((void**)&rowptr, g_rowptr);
    cudaGetSymbolAddress((void**)&cursor, g_cursor);
    cudaGetSymbolAddress((void**)&csrc, g_csrc);
    cudaGetSymbolAddress((void**)&cw, g_cw);

    const int EB = (EE + 255) / 256;
    const int MB = (NN + 127) / 128;        // 391 row-tiles
    const int SB = ((NN * 32) + 255) / 256; // spmm blocks (warp per node)

    // ---- build CSR per order ----
    for (int o = 0; o < OO; o++) {
        const int* dst = eidx + (size_t)o * 2 * EE;
        const int* src = dst + EE;
        int* cnt = cursor + (size_t)o * NN;
        int* rp  = rowptr + (size_t)o * (NN + 1);
        cudaMemsetAsync(cnt, 0, NN * sizeof(int), 0);
        csr_count<<<EB, 256>>>(dst, cnt);
        csr_scan<<<1, 1024>>>(cnt, rp);
        cudaMemcpyAsync(cnt, rp, NN * sizeof(int), cudaMemcpyDeviceToDevice, 0);
        csr_fill<<<EB, 256>>>(dst, src, ew + (size_t)o * EE, cnt,
                              csrc + (size_t)o * EE, cw + (size_t)o * EE);
    }

    const float* hin = x;
    for (int l = 0; l < LL; l++) {
        for (int o = 0; o < OO; o++) {
            int lo = l * OO + o;
            // z = hin @ W_in[l,o] + b_in ; hid seed = fW[l,o,0]*z
            gemm_fused<<<MB, 256>>>(hin, 128,
                                    W_in + (size_t)lo * 128 * 128,
                                    b_in + (size_t)lo * 128,
                                    zA,
                                    xcat + (size_t)o * 128, fW + (size_t)lo * (KHOP + 1),
                                    nullptr, nullptr);
            float* zi = zA; float* zo = zB;
            for (int k = 0; k < KHOP; k++) {
                spmm_hop<<<SB, 256>>>(rowptr + (size_t)o * (NN + 1),
                                      csrc + (size_t)o * EE, cw + (size_t)o * EE,
                                      zi, zo,
                                      xcat + (size_t)o * 128,
                                      fW + (size_t)lo * (KHOP + 1) + (k + 1));
                float* t = zi; zi = zo; zo = t;
            }
        }
        // xc = xcat @ W_out[l] + b_out[l]
        gemm_fused<<<MB, 256>>>(xcat, 256,
                                W_out + (size_t)l * 256 * 128,
                                b_out + (size_t)l * 128,
                                xc, nullptr, nullptr, nullptr, nullptr);
        // tmp = relu(bn1(xc @ Wn1 + bn1))
        gemm_fused<<<MB, 256>>>(xc, 128,
                                Wn1 + (size_t)l * 128 * 128,
                                bn1 + (size_t)l * 128,
                                zA, nullptr, nullptr,
                                g1 + (size_t)l * 128, be1 + (size_t)l * 128);
        // h = relu(bn2(tmp @ Wn2 + bn2))
        gemm_fused<<<MB, 256>>>(zA, 128,
                                Wn2 + (size_t)l * 128 * 128,
                                bn2 + (size_t)l * 128,
                                hbuf, nullptr, nullptr,
                                g2 + (size_t)l * 128, be2 + (size_t)l * 128);
        hin = hbuf;
    }

    // global add pool + MLP head
    cudaMemsetAsync(pool, 0, GG * HH * sizeof(float), 0);
    pool_kernel<<<(NN * HH + 255) / 256, 256>>>(hbuf, batch, pool);
    head1<<<(GG * HH + 255) / 256, 256>>>(pool, W1, b1, p1);
    head2<<<(GG * CC + 255) / 256, 256>>>(p1, W2, b2, outp);
}

// round 3
// speedup vs baseline: 1.1852x; 1.1852x over previous
#include <cuda_runtime.h>
#include <cuda_fp16.h>
#include <stdint.h>

#define NN 50000
#define EE 800000
#define HH 128
#define CC 10
#define LL 3
#define OO 2
#define KHOP 10
#define GG 128

// ---------------- scratch (static device arrays; no allocation) ----------------
__device__ __half g_zA[(size_t)NN * HH];
__device__ __half g_zB[(size_t)NN * HH];
__device__ float  g_xcat[(size_t)NN * (OO * HH)];
__device__ float  g_xc[(size_t)NN * HH];
__device__ float  g_h[(size_t)NN * HH];
__device__ int    g_rowptr[OO * (NN + 1)];
__device__ int    g_cursor[OO * NN];
__device__ int    g_csrc[OO * EE];
__device__ float  g_cw[OO * EE];
__device__ float  g_pool[GG * HH];
__device__ float  g_p1[GG * HH];

// ---------------- CSR build ----------------
__global__ void csr_count(const int* __restrict__ dst, int* __restrict__ cnt) {
    int e = blockIdx.x * blockDim.x + threadIdx.x;
    if (e < EE) atomicAdd(&cnt[dst[e]], 1);
}

__global__ void csr_scan(const int* __restrict__ cnt, int* __restrict__ rowptr) {
    __shared__ int sdata[1024];
    __shared__ int sbase;
    int t = threadIdx.x;
    if (t == 0) { rowptr[0] = 0; sbase = 0; }
    __syncthreads();
    for (int c = 0; c < NN; c += 1024) {
        int v = (c + t < NN) ? cnt[c + t] : 0;
        sdata[t] = v;
        __syncthreads();
        for (int off = 1; off < 1024; off <<= 1) {
            int add = (t >= off) ? sdata[t - off] : 0;
            __syncthreads();
            sdata[t] += add;
            __syncthreads();
        }
        if (c + t < NN) rowptr[c + t + 1] = sbase + sdata[t];
        __syncthreads();
        if (t == 0) sbase += sdata[1023];
        __syncthreads();
    }
}

__global__ void csr_fill(const int* __restrict__ dst, const int* __restrict__ src,
                         const float* __restrict__ w,
                         int* __restrict__ cursor,
                         int* __restrict__ csrc, float* __restrict__ cw) {
    int e = blockIdx.x * blockDim.x + threadIdx.x;
    if (e < EE) {
        int pos = atomicAdd(&cursor[dst[e]], 1);
        csrc[pos] = src[e];
        cw[pos]   = w[e];
    }
}

// ---------------- fused SGEMM: A[N,K]@B[K,128] (+bias, optional bn/relu, optional fp16 z + hid seed) ----------------
__global__ __launch_bounds__(256) void gemm_fused(
    const float* __restrict__ A, int K,
    const float* __restrict__ B,
    const float* __restrict__ bias,
    float* __restrict__ out32,              // fp32 output (may be null if out16 used)
    __half* __restrict__ out16,             // fp16 z output (may be null)
    float* __restrict__ hid,                // if non-null: hid[row*256+c] = fw0 * val
    const float* __restrict__ fw0p,
    const float* __restrict__ gam,          // if non-null: out = relu((acc+bias)*gam*RS + bet)
    const float* __restrict__ bet)
{
    __shared__ float As[8][128];
    __shared__ float Bs[8][128];
    const int tid = threadIdx.x;
    const int tx = tid & 15;
    const int ty = tid >> 4;
    const int rowBase = blockIdx.x * 128;

    float acc[8][8];
#pragma unroll
    for (int i = 0; i < 8; i++)
#pragma unroll
        for (int j = 0; j < 8; j++) acc[i][j] = 0.f;

    const int ar = tid >> 1;
    const int ac = (tid & 1) * 4;
    const int br = tid >> 5;
    const int bc = (tid & 31) * 4;
    const int arow = rowBase + ar;
    const bool avalid = (arow < NN);
    const float* Aptr = A + (size_t)arow * K + ac;
    const float* Bptr = B + (size_t)br * 128 + bc;

    for (int k0 = 0; k0 < K; k0 += 8) {
        float4 av = avalid ? *(const float4*)(Aptr + k0) : make_float4(0.f, 0.f, 0.f, 0.f);
        float4 bv = *(const float4*)(Bptr + (size_t)k0 * 128);
        As[ac + 0][ar] = av.x; As[ac + 1][ar] = av.y;
        As[ac + 2][ar] = av.z; As[ac + 3][ar] = av.w;
        *(float4*)&Bs[br][bc] = bv;
        __syncthreads();
#pragma unroll
        for (int k = 0; k < 8; k++) {
            float a[8], b[8];
            *(float4*)&a[0] = *(const float4*)&As[k][ty * 4];
            *(float4*)&a[4] = *(const float4*)&As[k][64 + ty * 4];
            *(float4*)&b[0] = *(const float4*)&Bs[k][tx * 4];
            *(float4*)&b[4] = *(const float4*)&Bs[k][64 + tx * 4];
#pragma unroll
            for (int i = 0; i < 8; i++)
#pragma unroll
                for (int j = 0; j < 8; j++)
                    acc[i][j] = fmaf(a[i], b[j], acc[i][j]);
        }
        __syncthreads();
    }

    const float RS = 0.9999950000374997f;  // 1/sqrt(1 + 1e-5)
    const float fw0 = (hid != nullptr) ? fw0p[0] : 0.f;

#pragma unroll
    for (int i = 0; i < 8; i++) {
        int r = (i < 4) ? (ty * 4 + i) : (64 + ty * 4 + (i - 4));
        int grow = rowBase + r;
        if (grow >= NN) continue;
#pragma unroll
        for (int jh = 0; jh < 2; jh++) {
            int cbase = jh * 64 + tx * 4;
            float4 v;
            float* vp = &v.x;
#pragma unroll
            for (int j = 0; j < 4; j++) {
                int c = cbase + j;
                float t = acc[i][jh * 4 + j] + bias[c];
                if (gam) t = fmaxf(t * gam[c] * RS + bet[c], 0.f);
                vp[j] = t;
            }
            if (out32)
                *(float4*)(out32 + (size_t)grow * 128 + cbase) = v;
            if (out16) {
                __half2 h0 = __floats2half2_rn(v.x, v.y);
                __half2 h1 = __floats2half2_rn(v.z, v.w);
                uint2 pk = make_uint2(*(uint32_t*)&h0, *(uint32_t*)&h1);
                *(uint2*)(out16 + (size_t)grow * 128 + cbase) = pk;
            }
            if (hid) {
                float4 hv = make_float4(fw0 * v.x, fw0 * v.y, fw0 * v.z, fw0 * v.w);
                *(float4*)(hid + (size_t)grow * 256 + cbase) = hv;
            }
        }
    }
}

// ---------------- SpMM hop (fp16 z, fp32 accumulate): zout[i]=sum w*zin[src]; hid[i]+=fw*zout ----------------
__global__ __launch_bounds__(256) void spmm_hop(
    const int* __restrict__ rowptr,
    const int* __restrict__ csrc,
    const float* __restrict__ cw,
    const __half* __restrict__ zin,
    __half* __restrict__ zout,
    float* __restrict__ hid,        // pre-offset by order, row stride 256
    const float* __restrict__ fwp)
{
    int warp = (blockIdx.x * blockDim.x + threadIdx.x) >> 5;
    int lane = threadIdx.x & 31;
    if (warp >= NN) return;
    int beg = rowptr[warp], end = rowptr[warp + 1];

    float ax = 0.f, ay = 0.f, az = 0.f, aw = 0.f;
    int e = beg;
    for (; e + 4 <= end; e += 4) {
        int s0 = csrc[e], s1 = csrc[e + 1], s2 = csrc[e + 2], s3 = csrc[e + 3];
        float w0 = cw[e], w1 = cw[e + 1], w2 = cw[e + 2], w3 = cw[e + 3];
        uint2 u0 = *(const uint2*)(zin + (size_t)s0 * 128 + lane * 4);
        uint2 u1 = *(const uint2*)(zin + (size_t)s1 * 128 + lane * 4);
        uint2 u2 = *(const uint2*)(zin + (size_t)s2 * 128 + lane * 4);
        uint2 u3 = *(const uint2*)(zin + (size_t)s3 * 128 + lane * 4);
        float2 a0 = __half22float2(*(__half2*)&u0.x), b0 = __half22float2(*(__half2*)&u0.y);
        float2 a1 = __half22float2(*(__half2*)&u1.x), b1 = __half22float2(*(__half2*)&u1.y);
        float2 a2 = __half22float2(*(__half2*)&u2.x), b2 = __half22float2(*(__half2*)&u2.y);
        float2 a3 = __half22float2(*(__half2*)&u3.x), b3 = __half22float2(*(__half2*)&u3.y);
        ax = fmaf(w0, a0.x, fmaf(w1, a1.x, fmaf(w2, a2.x, fmaf(w3, a3.x, ax))));
        ay = fmaf(w0, a0.y, fmaf(w1, a1.y, fmaf(w2, a2.y, fmaf(w3, a3.y, ay))));
        az = fmaf(w0, b0.x, fmaf(w1, b1.x, fmaf(w2, b2.x, fmaf(w3, b3.x, az))));
        aw = fmaf(w0, b0.y, fmaf(w1, b1.y, fmaf(w2, b2.y, fmaf(w3, b3.y, aw))));
    }
    for (; e < end; ++e) {
        int s = csrc[e];
        float w = cw[e];
        uint2 u = *(const uint2*)(zin + (size_t)s * 128 + lane * 4);
        float2 a = __half22float2(*(__half2*)&u.x), b = __half22float2(*(__half2*)&u.y);
        ax = fmaf(w, a.x, ax); ay = fmaf(w, a.y, ay);
        az = fmaf(w, b.x, az); aw = fmaf(w, b.y, aw);
    }

    __half2 h0 = __floats2half2_rn(ax, ay);
    __half2 h1 = __floats2half2_rn(az, aw);
    uint2 pk = make_uint2(*(uint32_t*)&h0, *(uint32_t*)&h1);
    *(uint2*)(zout + (size_t)warp * 128 + lane * 4) = pk;

    float fw = fwp[0];
    size_t ho = (size_t)warp * 256 + lane * 4;
    float4 hv = *(float4*)(hid + ho);
    hv.x = fmaf(fw, ax, hv.x); hv.y = fmaf(fw, ay, hv.y);
    hv.z = fmaf(fw, az, hv.z); hv.w = fmaf(fw, aw, hv.w);
    *(float4*)(hid + ho) = hv;
}

// ---------------- pooling + head ----------------
__global__ void pool_kernel(const float* __restrict__ h, const int* __restrict__ batch,
                            float* __restrict__ p) {
    int idx = blockIdx.x * blockDim.x + threadIdx.x;
    if (idx >= NN * HH) return;
    int node = idx >> 7;
    int f = idx & 127;
    atomicAdd(&p[batch[node] * HH + f], h[idx]);
}

__global__ void head1(const float* __restrict__ p, const float* __restrict__ W1,
                      const float* __restrict__ b1, float* __restrict__ p1) {
    int i = blockIdx.x * blockDim.x + threadIdx.x;
    if (i >= GG * HH) return;
    int g = i >> 7, j = i & 127;
    float acc = b1[j];
    for (int k = 0; k < HH; k++)
        acc = fmaf(p[g * HH + k], W1[k * HH + j], acc);
    p1[i] = fmaxf(acc, 0.f);
}

__global__ void head2(const float* __restrict__ p1, const float* __restrict__ W2,
                      const float* __restrict__ b2, float* __restrict__ outp) {
    int i = blockIdx.x * blockDim.x + threadIdx.x;
    if (i >= GG * CC) return;
    int g = i / CC, j = i % CC;
    float acc = b2[j];
    for (int k = 0; k < HH; k++)
        acc = fmaf(p1[g * HH + k], W2[k * CC + j], acc);
    outp[i] = acc;
}

// ---------------- host orchestration ----------------
extern "C" void kernel_launch(void* const* d_in, const int* in_sizes, int n_in,
                              void* d_out, int out_size) {
    const float* x      = (const float*)d_in[0];
    const int*   eidx   = (const int*)  d_in[1];
    const float* ew     = (const float*)d_in[2];
    const int*   batch  = (const int*)  d_in[3];
    const float* W_in   = (const float*)d_in[4];
    const float* b_in   = (const float*)d_in[5];
    const float* fW     = (const float*)d_in[6];
    const float* W_out  = (const float*)d_in[7];
    const float* b_out  = (const float*)d_in[8];
    const float* Wn1    = (const float*)d_in[9];
    const float* bn1    = (const float*)d_in[10];
    const float* g1     = (const float*)d_in[11];
    const float* be1    = (const float*)d_in[12];
    const float* Wn2    = (const float*)d_in[13];
    const float* bn2    = (const float*)d_in[14];
    const float* g2     = (const float*)d_in[15];
    const float* be2    = (const float*)d_in[16];
    const float* W1     = (const float*)d_in[17];
    const float* b1     = (const float*)d_in[18];
    const float* W2     = (const float*)d_in[19];
    const float* b2     = (const float*)d_in[20];
    float* outp = (float*)d_out;

    __half *zA, *zB;
    float *xcat, *xc, *hbuf, *pool, *p1, *cw;
    int *rowptr, *cursor, *csrc;
    cudaGetSymbolAddress((void**)&zA, g_zA);
    cudaGetSymbolAddress((void**)&zB, g_zB);
    cudaGetSymbolAddress((void**)&xcat, g_xcat);
    cudaGetSymbolAddress((void**)&xc, g_xc);
    cudaGetSymbolAddress((void**)&hbuf, g_h);
    cudaGetSymbolAddress((void**)&pool, g_pool);
    cudaGetSymbolAddress((void**)&p1, g_p1);
    cudaGetSymbolAddress((void**)&rowptr, g_rowptr);
    cudaGetSymbolAddress((void**)&cursor, g_cursor);
    cudaGetSymbolAddress((void**)&csrc, g_csrc);
    cudaGetSymbolAddress((void**)&cw, g_cw);

    const int EB = (EE + 255) / 256;
    const int MB = (NN + 127) / 128;        // 391 row-tiles
    const int SB = ((NN * 32) + 255) / 256; // warp per node

    // ---- build CSR per order ----
    for (int o = 0; o < OO; o++) {
        const int* dst = eidx + (size_t)o * 2 * EE;
        const int* src = dst + EE;
        int* cnt = cursor + (size_t)o * NN;
        int* rp  = rowptr + (size_t)o * (NN + 1);
        cudaMemsetAsync(cnt, 0, NN * sizeof(int), 0);
        csr_count<<<EB, 256>>>(dst, cnt);
        csr_scan<<<1, 1024>>>(cnt, rp);
        cudaMemcpyAsync(cnt, rp, NN * sizeof(int), cudaMemcpyDeviceToDevice, 0);
        csr_fill<<<EB, 256>>>(dst, src, ew + (size_t)o * EE, cnt,
                              csrc + (size_t)o * EE, cw + (size_t)o * EE);
    }

    const float* hin = x;
    for (int l = 0; l < LL; l++) {
        for (int o = 0; o < OO; o++) {
            int lo = l * OO + o;
            // z = hin @ W_in[l,o] + b_in (fp16 z out); hid seed = fW[l,o,0]*z (fp32)
            gemm_fused<<<MB, 256>>>(hin, 128,
                                    W_in + (size_t)lo * 128 * 128,
                                    b_in + (size_t)lo * 128,
                                    nullptr, zA,
                                    xcat + (size_t)o * 128, fW + (size_t)lo * (KHOP + 1),
                                    nullptr, nullptr);
            __half* zi = zA; __half* zo = zB;
            for (int k = 0; k < KHOP; k++) {
                spmm_hop<<<SB, 256>>>(rowptr + (size_t)o * (NN + 1),
                                      csrc + (size_t)o * EE, cw + (size_t)o * EE,
                                      zi, zo,
                                      xcat + (size_t)o * 128,
                                      fW + (size_t)lo * (KHOP + 1) + (k + 1));
                __half* t = zi; zi = zo; zo = t;
            }
        }
        // xc = xcat @ W_out[l] + b_out[l]
        gemm_fused<<<MB, 256>>>(xcat, 256,
                                W_out + (size_t)l * 256 * 128,
                                b_out + (size_t)l * 128,
                                xc, nullptr, nullptr, nullptr, nullptr, nullptr);
        // tmp = relu(bn1(xc @ Wn1 + bn1))  -> reuse xcat[:,:128] as fp32 scratch
        gemm_fused<<<MB, 256>>>(xc, 128,
                                Wn1 + (size_t)l * 128 * 128,
                                bn1 + (size_t)l * 128,
                                xcat, nullptr, nullptr, nullptr,
                                g1 + (size_t)l * 128, be1 + (size_t)l * 128);
        // h = relu(bn2(tmp @ Wn2 + bn2))
        gemm_fused<<<MB, 256>>>(xcat, 128,
                                Wn2 + (size_t)l * 128 * 128,
                                bn2 + (size_t)l * 128,
                                hbuf, nullptr, nullptr, nullptr,
                                g2 + (size_t)l * 128, be2 + (size_t)l * 128);
        hin = hbuf;
    }

    cudaMemsetAsync(pool, 0, GG * HH * sizeof(float), 0);
    pool_kernel<<<(NN * HH + 255) / 256, 256>>>(hbuf, batch, pool);
    head1<<<(GG * HH + 255) / 256, 256>>>(pool, W1, b1, p1);
    head2<<<(GG * CC + 255) / 256, 256>>>(p1, W2, b2, outp);
}

// round 4
// speedup vs baseline: 1.5425x; 1.3014x over previous
#include <cuda_runtime.h>
#include <cuda_fp16.h>
#include <mma.h>
#include <stdint.h>

using namespace nvcuda;

#define NN 50000
#define EE 800000
#define HH 128
#define CC 10
#define LL 3
#define OO 2
#define KHOP 10
#define GG 128
#define NH ((size_t)NN * HH)

// ---------------- scratch (static device arrays; no allocation) ----------------
__device__ __half g_x16[NH];
__device__ __half g_zh[(KHOP + 1) * NH];          // z-history per (l,o) pass
__device__ __half g_xcat16[(size_t)NN * 256];     // combined hid, both orders
__device__ __half g_xc16[NH];
__device__ __half g_t16[NH];
__device__ __half g_h16[NH];
__device__ __half g_w16[LL * OO * HH * HH + LL * 256 * HH + 2 * LL * HH * HH]; // Win|Wout|Wn1|Wn2
__device__ int    g_rowptr[OO * (NN + 1)];
__device__ int    g_cursor[OO * NN];
__device__ int    g_csrc[OO * EE];
__device__ float  g_cw[OO * EE];
__device__ float  g_pool[GG * HH];
__device__ float  g_p1[GG * HH];

// ---------------- CSR build ----------------
__global__ void csr_count(const int* __restrict__ dst, int* __restrict__ cnt) {
    int e = blockIdx.x * blockDim.x + threadIdx.x;
    if (e < EE) atomicAdd(&cnt[dst[e]], 1);
}

__global__ void csr_scan(const int* __restrict__ cnt, int* __restrict__ rowptr) {
    __shared__ int sdata[1024];
    __shared__ int sbase;
    int t = threadIdx.x;
    if (t == 0) { rowptr[0] = 0; sbase = 0; }
    __syncthreads();
    for (int c = 0; c < NN; c += 1024) {
        int v = (c + t < NN) ? cnt[c + t] : 0;
        sdata[t] = v;
        __syncthreads();
        for (int off = 1; off < 1024; off <<= 1) {
            int add = (t >= off) ? sdata[t - off] : 0;
            __syncthreads();
            sdata[t] += add;
            __syncthreads();
        }
        if (c + t < NN) rowptr[c + t + 1] = sbase + sdata[t];
        __syncthreads();
        if (t == 0) sbase += sdata[1023];
        __syncthreads();
    }
}

__global__ void csr_fill(const int* __restrict__ dst, const int* __restrict__ src,
                         const float* __restrict__ w,
                         int* __restrict__ cursor,
                         int* __restrict__ csrc, float* __restrict__ cw) {
    int e = blockIdx.x * blockDim.x + threadIdx.x;
    if (e < EE) {
        int pos = atomicAdd(&cursor[dst[e]], 1);
        csrc[pos] = src[e];
        cw[pos]   = w[e];
    }
}

// ---------------- casts ----------------
__global__ void cast_f2h(const float* __restrict__ src, __half* __restrict__ dst, int n) {
    int i = blockIdx.x * blockDim.x + threadIdx.x;
    int i4 = i * 4;
    if (i4 + 3 < n) {
        float4 v = *(const float4*)(src + i4);
        __half2 h0 = __floats2half2_rn(v.x, v.y);
        __half2 h1 = __floats2half2_rn(v.z, v.w);
        *(uint2*)(dst + i4) = make_uint2(*(uint32_t*)&h0, *(uint32_t*)&h1);
    } else {
        for (int j = i4; j < n; j++) dst[j] = __float2half(src[j]);
    }
}

// ---------------- wmma fp16 GEMM: out16[N,128] = relu?(bn?(A16[N,K]@B16[K,128] + bias)) ----------------
__global__ __launch_bounds__(256) void gemm16(
    const __half* __restrict__ A, int K, int lda,
    const __half* __restrict__ B,            // [K,128] row-major fp16
    const float* __restrict__ bias,
    __half* __restrict__ out,                // [N,128]
    const float* __restrict__ gam,           // if non-null: relu(bn)
    const float* __restrict__ bet)
{
    extern __shared__ char smem[];
    __half* As = (__half*)smem;               // [128][136]
    __half* Bs = (__half*)(smem + 128 * 136 * 2);
    float*  Cs = (float*)smem;                // [128][132] (reused after compute)

    const int tid = threadIdx.x;
    const int warp = tid >> 5;
    const int warpM = warp >> 1;   // 0..3 -> 32 rows each
    const int warpN = warp & 1;    // 0..1 -> 64 cols each
    const int rowBase = blockIdx.x * 128;

    wmma::fragment<wmma::accumulator, 16, 16, 16, float> acc[2][4];
#pragma unroll
    for (int i = 0; i < 2; i++)
#pragma unroll
        for (int j = 0; j < 4; j++) wmma::fill_fragment(acc[i][j], 0.f);

    const int nchunk = K >> 7;
    for (int kc = 0; kc < nchunk; kc++) {
        // load A chunk [128][128] and B chunk [128][128]
#pragma unroll
        for (int it = 0; it < 8; it++) {
            int idx = it * 256 + tid;
            int r = idx >> 4;
            int c8 = (idx & 15) * 8;
            int grow = rowBase + r;
            uint4 av = make_uint4(0, 0, 0, 0);
            if (grow < NN) av = *(const uint4*)(A + (size_t)grow * lda + kc * 128 + c8);
            *(uint4*)(As + r * 136 + c8) = av;
            uint4 bv = *(const uint4*)(B + (size_t)(kc * 128 + r) * 128 + c8);
            *(uint4*)(Bs + r * 136 + c8) = bv;
        }
        __syncthreads();
#pragma unroll
        for (int ks = 0; ks < 8; ks++) {
            int k0 = ks * 16;
            wmma::fragment<wmma::matrix_a, 16, 16, 16, __half, wmma::row_major> af[2];
            wmma::fragment<wmma::matrix_b, 16, 16, 16, __half, wmma::row_major> bf[4];
#pragma unroll
            for (int i = 0; i < 2; i++)
                wmma::load_matrix_sync(af[i], As + (warpM * 32 + i * 16) * 136 + k0, 136);
#pragma unroll
            for (int j = 0; j < 4; j++)
                wmma::load_matrix_sync(bf[j], Bs + k0 * 136 + warpN * 64 + j * 16, 136);
#pragma unroll
            for (int i = 0; i < 2; i++)
#pragma unroll
                for (int j = 0; j < 4; j++)
                    wmma::mma_sync(acc[i][j], af[i], bf[j], acc[i][j]);
        }
        __syncthreads();
    }

    // store accumulators to SMEM
#pragma unroll
    for (int i = 0; i < 2; i++)
#pragma unroll
        for (int j = 0; j < 4; j++)
            wmma::store_matrix_sync(Cs + (warpM * 32 + i * 16) * 132 + warpN * 64 + j * 16,
                                    acc[i][j], 132, wmma::mem_row_major);
    __syncthreads();

    // epilogue: thread -> (row = tid>>1, 64-col half = tid&1)
    const float RS = 0.9999950000374997f;  // 1/sqrt(1+1e-5)
    const int r = tid >> 1;
    const int cb0 = (tid & 1) * 64;
    const int grow = rowBase + r;
    if (grow < NN) {
#pragma unroll
        for (int j = 0; j < 8; j++) {
            int c0 = cb0 + j * 8;
            float4 v0 = *(const float4*)(Cs + r * 132 + c0);
            float4 v1 = *(const float4*)(Cs + r * 132 + c0 + 4);
            float t[8] = {v0.x, v0.y, v0.z, v0.w, v1.x, v1.y, v1.z, v1.w};
#pragma unroll
            for (int q = 0; q < 8; q++) {
                int c = c0 + q;
                t[q] += bias[c];
                if (gam) t[q] = fmaxf(t[q] * gam[c] * RS + bet[c], 0.f);
            }
            __half2 h0 = __floats2half2_rn(t[0], t[1]);
            __half2 h1 = __floats2half2_rn(t[2], t[3]);
            __half2 h2 = __floats2half2_rn(t[4], t[5]);
            __half2 h3 = __floats2half2_rn(t[6], t[7]);
            *(uint4*)(out + (size_t)grow * 128 + c0) =
                make_uint4(*(uint32_t*)&h0, *(uint32_t*)&h1, *(uint32_t*)&h2, *(uint32_t*)&h3);
        }
    }
}

// ---------------- SpMM hop (fp16 z, fp32 accumulate): zout[i]=sum w*zin[src] ----------------
__global__ __launch_bounds__(256) void spmm_hop(
    const int* __restrict__ rowptr,
    const int* __restrict__ csrc,
    const float* __restrict__ cw,
    const __half* __restrict__ zin,
    __half* __restrict__ zout)
{
    int warp = (blockIdx.x * blockDim.x + threadIdx.x) >> 5;
    int lane = threadIdx.x & 31;
    if (warp >= NN) return;
    int beg = rowptr[warp], end = rowptr[warp + 1];

    float ax = 0.f, ay = 0.f, az = 0.f, aw = 0.f;
    int e = beg;
    for (; e + 4 <= end; e += 4) {
        int s0 = csrc[e], s1 = csrc[e + 1], s2 = csrc[e + 2], s3 = csrc[e + 3];
        float w0 = cw[e], w1 = cw[e + 1], w2 = cw[e + 2], w3 = cw[e + 3];
        uint2 u0 = *(const uint2*)(zin + (size_t)s0 * 128 + lane * 4);
        uint2 u1 = *(const uint2*)(zin + (size_t)s1 * 128 + lane * 4);
        uint2 u2 = *(const uint2*)(zin + (size_t)s2 * 128 + lane * 4);
        uint2 u3 = *(const uint2*)(zin + (size_t)s3 * 128 + lane * 4);
        float2 a0 = __half22float2(*(__half2*)&u0.x), b0 = __half22float2(*(__half2*)&u0.y);
        float2 a1 = __half22float2(*(__half2*)&u1.x), b1 = __half22float2(*(__half2*)&u1.y);
        float2 a2 = __half22float2(*(__half2*)&u2.x), b2 = __half22float2(*(__half2*)&u2.y);
        float2 a3 = __half22float2(*(__half2*)&u3.x), b3 = __half22float2(*(__half2*)&u3.y);
        ax = fmaf(w0, a0.x, fmaf(w1, a1.x, fmaf(w2, a2.x, fmaf(w3, a3.x, ax))));
        ay = fmaf(w0, a0.y, fmaf(w1, a1.y, fmaf(w2, a2.y, fmaf(w3, a3.y, ay))));
        az = fmaf(w0, b0.x, fmaf(w1, b1.x, fmaf(w2, b2.x, fmaf(w3, b3.x, az))));
        aw = fmaf(w0, b0.y, fmaf(w1, b1.y, fmaf(w2, b2.y, fmaf(w3, b3.y, aw))));
    }
    for (; e < end; ++e) {
        int s = csrc[e];
        float w = cw[e];
        uint2 u = *(const uint2*)(zin + (size_t)s * 128 + lane * 4);
        float2 a = __half22float2(*(__half2*)&u.x), b = __half22float2(*(__half2*)&u.y);
        ax = fmaf(w, a.x, ax); ay = fmaf(w, a.y, ay);
        az = fmaf(w, b.x, az); aw = fmaf(w, b.y, aw);
    }

    __half2 h0 = __floats2half2_rn(ax, ay);
    __half2 h1 = __floats2half2_rn(az, aw);
    *(uint2*)(zout + (size_t)warp * 128 + lane * 4) = make_uint2(*(uint32_t*)&h0, *(uint32_t*)&h1);
}

// ---------------- combine: xcat16[n, o*128+c] = sum_k fW[k] * zh[k][n*128+c] ----------------
__global__ void combine_hid(const __half* __restrict__ zh,
                            const float* __restrict__ fw,   // 11 floats
                            __half* __restrict__ xcat)      // pre-offset by order, stride 256
{
    int i = blockIdx.x * blockDim.x + threadIdx.x;   // over NH/8 uint4 groups
    if (i >= (int)(NH / 8)) return;
    float facc[8] = {0, 0, 0, 0, 0, 0, 0, 0};
#pragma unroll
    for (int k = 0; k <= KHOP; k++) {
        float f = fw[k];
        uint4 u = *(const uint4*)(zh + (size_t)k * NH + (size_t)i * 8);
        float2 p0 = __half22float2(*(__half2*)&u.x);
        float2 p1 = __half22float2(*(__half2*)&u.y);
        float2 p2 = __half22float2(*(__half2*)&u.z);
        float2 p3 = __half22float2(*(__half2*)&u.w);
        facc[0] = fmaf(f, p0.x, facc[0]); facc[1] = fmaf(f, p0.y, facc[1]);
        facc[2] = fmaf(f, p1.x, facc[2]); facc[3] = fmaf(f, p1.y, facc[3]);
        facc[4] = fmaf(f, p2.x, facc[4]); facc[5] = fmaf(f, p2.y, facc[5]);
        facc[6] = fmaf(f, p3.x, facc[6]); facc[7] = fmaf(f, p3.y, facc[7]);
    }
    size_t elem = (size_t)i * 8;
    size_t row = elem >> 7;
    int col = (int)(elem & 127);
    __half2 h0 = __floats2half2_rn(facc[0], facc[1]);
    __half2 h1 = __floats2half2_rn(facc[2], facc[3]);
    __half2 h2 = __floats2half2_rn(facc[4], facc[5]);
    __half2 h3 = __floats2half2_rn(facc[6], facc[7]);
    *(uint4*)(xcat + row * 256 + col) =
        make_uint4(*(uint32_t*)&h0, *(uint32_t*)&h1, *(uint32_t*)&h2, *(uint32_t*)&h3);
}

// ---------------- pooling + head ----------------
__global__ void pool_kernel(const __half* __restrict__ h, const int* __restrict__ batch,
                            float* __restrict__ p) {
    int idx = blockIdx.x * blockDim.x + threadIdx.x;
    if (idx >= NN * HH) return;
    int node = idx >> 7;
    int f = idx & 127;
    atomicAdd(&p[batch[node] * HH + f], __half2float(h[idx]));
}

__global__ void head1(const float* __restrict__ p, const float* __restrict__ W1,
                      const float* __restrict__ b1, float* __restrict__ p1) {
    int i = blockIdx.x * blockDim.x + threadIdx.x;
    if (i >= GG * HH) return;
    int g = i >> 7, j = i & 127;
    float acc = b1[j];
    for (int k = 0; k < HH; k++)
        acc = fmaf(p[g * HH + k], W1[k * HH + j], acc);
    p1[i] = fmaxf(acc, 0.f);
}

__global__ void head2(const float* __restrict__ p1, const float* __restrict__ W2,
                      const float* __restrict__ b2, float* __restrict__ outp) {
    int i = blockIdx.x * blockDim.x + threadIdx.x;
    if (i >= GG * CC) return;
    int g = i / CC, j = i % CC;
    float acc = b2[j];
    for (int k = 0; k < HH; k++)
        acc = fmaf(p1[g * HH + k], W2[k * CC + j], acc);
    outp[i] = acc;
}

// ---------------- host orchestration ----------------
extern "C" void kernel_launch(void* const* d_in, const int* in_sizes, int n_in,
                              void* d_out, int out_size) {
    const float* x      = (const float*)d_in[0];
    const int*   eidx   = (const int*)  d_in[1];
    const float* ew     = (const float*)d_in[2];
    const int*   batch  = (const int*)  d_in[3];
    const float* W_in   = (const float*)d_in[4];
    const float* b_in   = (const float*)d_in[5];
    const float* fW     = (const float*)d_in[6];
    const float* W_out  = (const float*)d_in[7];
    const float* b_out  = (const float*)d_in[8];
    const float* Wn1    = (const float*)d_in[9];
    const float* bn1    = (const float*)d_in[10];
    const float* g1     = (const float*)d_in[11];
    const float* be1    = (const float*)d_in[12];
    const float* Wn2    = (const float*)d_in[13];
    const float* bn2    = (const float*)d_in[14];
    const float* g2     = (const float*)d_in[15];
    const float* be2    = (const float*)d_in[16];
    const float* W1     = (const float*)d_in[17];
    const float* b1     = (const float*)d_in[18];
    const float* W2     = (const float*)d_in[19];
    const float* b2     = (const float*)d_in[20];
    float* outp = (float*)d_out;

    __half *x16, *zh, *xcat16, *xc16, *t16, *h16, *w16;
    float *pool, *p1, *cw;
    int *rowptr, *cursor, *csrc;
    cudaGetSymbolAddress((void**)&x16, g_x16);
    cudaGetSymbolAddress((void**)&zh, g_zh);
    cudaGetSymbolAddress((void**)&xcat16, g_xcat16);
    cudaGetSymbolAddress((void**)&xc16, g_xc16);
    cudaGetSymbolAddress((void**)&t16, g_t16);
    cudaGetSymbolAddress((void**)&h16, g_h16);
    cudaGetSymbolAddress((void**)&w16, g_w16);
    cudaGetSymbolAddress((void**)&pool, g_pool);
    cudaGetSymbolAddress((void**)&p1, g_p1);
    cudaGetSymbolAddress((void**)&rowptr, g_rowptr);
    cudaGetSymbolAddress((void**)&cursor, g_cursor);
    cudaGetSymbolAddress((void**)&csrc, g_csrc);
    cudaGetSymbolAddress((void**)&cw, g_cw);

    // fp16 weight regions inside g_w16
    const size_t WIN_SZ  = (size_t)LL * OO * HH * HH;   // 98304
    const size_t WOUT_SZ = (size_t)LL * 256 * HH;       // 98304
    const size_t WN_SZ   = (size_t)LL * HH * HH;        // 49152
    __half* Win16  = w16;
    __half* Wout16 = w16 + WIN_SZ;
    __half* Wn116  = w16 + WIN_SZ + WOUT_SZ;
    __half* Wn216  = w16 + WIN_SZ + WOUT_SZ + WN_SZ;

    const int EB = (EE + 255) / 256;
    const int MB = (NN + 127) / 128;         // 391 tiles
    const int SB = ((NN * 32) + 255) / 256;  // warp per node
    const int CB = ((int)(NH / 8) + 255) / 256;
    const int GEMM_SMEM = 128 * 136 * 2 * 2; // 69632

    cudaFuncSetAttribute(gemm16, cudaFuncAttributeMaxDynamicSharedMemorySize, GEMM_SMEM);

    // ---- casts: weights + x ----
    cast_f2h<<<(int)((WIN_SZ / 4 + 255) / 256), 256>>>(W_in, Win16, (int)WIN_SZ);
    cast_f2h<<<(int)((WOUT_SZ / 4 + 255) / 256), 256>>>(W_out, Wout16, (int)WOUT_SZ);
    cast_f2h<<<(int)((WN_SZ / 4 + 255) / 256), 256>>>(Wn1, Wn116, (int)WN_SZ);
    cast_f2h<<<(int)((WN_SZ / 4 + 255) / 256), 256>>>(Wn2, Wn216, (int)WN_SZ);
    cast_f2h<<<(int)((NH / 4 + 255) / 256), 256>>>(x, x16, (int)NH);

    // ---- build CSR per order ----
    for (int o = 0; o < OO; o++) {
        const int* dst = eidx + (size_t)o * 2 * EE;
        const int* src = dst + EE;
        int* cnt = cursor + (size_t)o * NN;
        int* rp  = rowptr + (size_t)o * (NN + 1);
        cudaMemsetAsync(cnt, 0, NN * sizeof(int), 0);
        csr_count<<<EB, 256>>>(dst, cnt);
        csr_scan<<<1, 1024>>>(cnt, rp);
        cudaMemcpyAsync(cnt, rp, NN * sizeof(int), cudaMemcpyDeviceToDevice, 0);
        csr_fill<<<EB, 256>>>(dst, src, ew + (size_t)o * EE, cnt,
                              csrc + (size_t)o * EE, cw + (size_t)o * EE);
    }

    const __half* hin = x16;
    for (int l = 0; l < LL; l++) {
        for (int o = 0; o < OO; o++) {
            int lo = l * OO + o;
            // z0 = hin @ Win + b_in  -> zh slot 0
            gemm16<<<MB, 256, GEMM_SMEM>>>(hin, 128, 128,
                                           Win16 + (size_t)lo * HH * HH,
                                           b_in + (size_t)lo * HH,
                                           zh, nullptr, nullptr);
            for (int k = 0; k < KHOP; k++)
                spmm_hop<<<SB, 256>>>(rowptr + (size_t)o * (NN + 1),
                                      csrc + (size_t)o * EE, cw + (size_t)o * EE,
                                      zh + (size_t)k * NH, zh + (size_t)(k + 1) * NH);
            combine_hid<<<CB, 256>>>(zh, fW + (size_t)lo * (KHOP + 1),
                                     xcat16 + (size_t)o * 128);
        }
        // xc = xcat @ Wout + b_out
        gemm16<<<MB, 256, GEMM_SMEM>>>(xcat16, 256, 256,
                                       Wout16 + (size_t)l * 256 * HH,
                                       b_out + (size_t)l * HH,
                                       xc16, nullptr, nullptr);
        // t = relu(bn1(xc @ Wn1 + bn1))
        gemm16<<<MB, 256, GEMM_SMEM>>>(xc16, 128, 128,
                                       Wn116 + (size_t)l * HH * HH,
                                       bn1 + (size_t)l * HH,
                                       t16, g1 + (size_t)l * HH, be1 + (size_t)l * HH);
        // h = relu(bn2(t @ Wn2 + bn2))
        gemm16<<<MB, 256, GEMM_SMEM>>>(t16, 128, 128,
                                       Wn216 + (size_t)l * HH * HH,
                                       bn2 + (size_t)l * HH,
                                       h16, g2 + (size_t)l * HH, be2 + (size_t)l * HH);
        hin = h16;
    }

    cudaMemsetAsync(pool, 0, GG * HH * sizeof(float), 0);
    pool_kernel<<<(NN * HH + 255) / 256, 256>>>(h16, batch, pool);
    head1<<<(GG * HH + 255) / 256, 256>>>(pool, W1, b1, p1);
    head2<<<(GG * CC + 255) / 256, 256>>>(p1, W2, b2, outp);
}

// round 5
// speedup vs baseline: 1.6278x; 1.0553x over previous
#include <cuda_runtime.h>
#include <cuda_fp16.h>
#include <mma.h>
#include <stdint.h>

using namespace nvcuda;

#define NN 50000
#define EE 800000
#define HH 128
#define CC 10
#define LL 3
#define OO 2
#define KHOP 10
#define GG 128
#define NH ((size_t)NN * HH)
#define ZSTRIDE ((size_t)(KHOP + 1) * NH)

// ---------------- scratch ----------------
__device__ __half g_x16[NH];
__device__ __half g_zh[OO * ZSTRIDE];             // z-history, both orders
__device__ __half g_xcat16[(size_t)NN * 256];
__device__ __half g_t16[NH];
__device__ __half g_h16[NH];
__device__ __half g_win16[LL * OO * HH * HH];
__device__ __half g_wfold16[LL * 256 * HH];
__device__ float  g_bfold[LL * HH];
__device__ __half g_wn216[LL * HH * HH];
__device__ int    g_rowptr[OO * (NN + 1)];
__device__ int    g_cursor[OO * NN];
__device__ int    g_csrc[OO * EE];
__device__ float  g_cw[OO * EE];
__device__ float  g_pool[GG * HH];
__device__ float  g_p1[GG * HH];

// ---------------- CSR build ----------------
__global__ void csr_count(const int* __restrict__ dst, int* __restrict__ cnt) {
    int e = blockIdx.x * blockDim.x + threadIdx.x;
    if (e < EE) atomicAdd(&cnt[dst[e]], 1);
}

__global__ void csr_scan(const int* __restrict__ cnt, int* __restrict__ rowptr) {
    __shared__ int sdata[1024];
    __shared__ int sbase;
    int t = threadIdx.x;
    if (t == 0) { rowptr[0] = 0; sbase = 0; }
    __syncthreads();
    for (int c = 0; c < NN; c += 1024) {
        int v = (c + t < NN) ? cnt[c + t] : 0;
        sdata[t] = v;
        __syncthreads();
        for (int off = 1; off < 1024; off <<= 1) {
            int add = (t >= off) ? sdata[t - off] : 0;
            __syncthreads();
            sdata[t] += add;
            __syncthreads();
        }
        if (c + t < NN) rowptr[c + t + 1] = sbase + sdata[t];
        __syncthreads();
        if (t == 0) sbase += sdata[1023];
        __syncthreads();
    }
}

__global__ void csr_fill(const int* __restrict__ dst, const int* __restrict__ src,
                         const float* __restrict__ w,
                         int* __restrict__ cursor,
                         int* __restrict__ csrc, float* __restrict__ cw) {
    int e = blockIdx.x * blockDim.x + threadIdx.x;
    if (e < EE) {
        int pos = atomicAdd(&cursor[dst[e]], 1);
        csrc[pos] = src[e];
        cw[pos]   = w[e];
    }
}

// ---------------- casts + weight prep ----------------
__global__ void cast_f2h(const float* __restrict__ src, __half* __restrict__ dst, int n) {
    int i = blockIdx.x * blockDim.x + threadIdx.x;
    int i4 = i * 4;
    if (i4 + 3 < n) {
        float4 v = *(const float4*)(src + i4);
        __half2 h0 = __floats2half2_rn(v.x, v.y);
        __half2 h1 = __floats2half2_rn(v.z, v.w);
        *(uint2*)(dst + i4) = make_uint2(*(uint32_t*)&h0, *(uint32_t*)&h1);
    } else {
        for (int j = i4; j < n; j++) dst[j] = __float2half(src[j]);
    }
}

// Wfold[l][k][j] = sum_m Wout[l][k][m] * Wn1[l][m][j]   (k<256)
__global__ void fold_w(const float* __restrict__ Wout, const float* __restrict__ Wn1,
                       __half* __restrict__ Wfold) {
    int l = blockIdx.y;
    int idx = blockIdx.x * blockDim.x + threadIdx.x;   // 256*128
    if (idx >= 256 * 128) return;
    int k = idx >> 7, j = idx & 127;
    const float* wo = Wout + (size_t)l * 256 * 128 + (size_t)k * 128;
    const float* wn = Wn1 + (size_t)l * 128 * 128 + j;
    float acc = 0.f;
#pragma unroll 8
    for (int m = 0; m < 128; m++) acc = fmaf(wo[m], wn[(size_t)m * 128], acc);
    Wfold[(size_t)l * 256 * 128 + idx] = __float2half(acc);
}

// bfold[l][j] = bn1[l][j] + sum_m b_out[l][m]*Wn1[l][m][j]
__global__ void fold_b(const float* __restrict__ b_out, const float* __restrict__ Wn1,
                       const float* __restrict__ bn1, float* __restrict__ bf) {
    int l = blockIdx.y;
    int j = threadIdx.x;
    const float* bo = b_out + (size_t)l * 128;
    const float* wn = Wn1 + (size_t)l * 128 * 128 + j;
    float acc = bn1[(size_t)l * 128 + j];
    for (int m = 0; m < 128; m++) acc = fmaf(bo[m], wn[(size_t)m * 128], acc);
    bf[(size_t)l * 128 + j] = acc;
}

// ---------------- wmma fp16 GEMM (multi-order via blockIdx.y) ----------------
__global__ __launch_bounds__(256) void gemm16(
    const __half* __restrict__ A, int K, int lda,
    const __half* __restrict__ Bb, size_t Bstride,
    const float* __restrict__ biasb, size_t biasStride,
    __half* __restrict__ outb, size_t outStride,
    const float* __restrict__ gam, const float* __restrict__ bet)
{
    extern __shared__ char smem[];
    __half* As = (__half*)smem;               // [128][136]
    __half* Bs = (__half*)(smem + 128 * 136 * 2);
    float*  Cs = (float*)smem;                // [128][132] (reused)

    const int o = blockIdx.y;
    const __half* B = Bb + (size_t)o * Bstride;
    const float* bias = biasb + (size_t)o * biasStride;
    __half* out = outb + (size_t)o * outStride;

    const int tid = threadIdx.x;
    const int warp = tid >> 5;
    const int warpM = warp >> 1;
    const int warpN = warp & 1;
    const int rowBase = blockIdx.x * 128;

    wmma::fragment<wmma::accumulator, 16, 16, 16, float> acc[2][4];
#pragma unroll
    for (int i = 0; i < 2; i++)
#pragma unroll
        for (int j = 0; j < 4; j++) wmma::fill_fragment(acc[i][j], 0.f);

    const int nchunk = K >> 7;
    for (int kc = 0; kc < nchunk; kc++) {
#pragma unroll
        for (int it = 0; it < 8; it++) {
            int idx = it * 256 + tid;
            int r = idx >> 4;
            int c8 = (idx & 15) * 8;
            int grow = rowBase + r;
            uint4 av = make_uint4(0, 0, 0, 0);
            if (grow < NN) av = *(const uint4*)(A + (size_t)grow * lda + kc * 128 + c8);
            *(uint4*)(As + r * 136 + c8) = av;
            uint4 bv = *(const uint4*)(B + (size_t)(kc * 128 + r) * 128 + c8);
            *(uint4*)(Bs + r * 136 + c8) = bv;
        }
        __syncthreads();
#pragma unroll
        for (int ks = 0; ks < 8; ks++) {
            int k0 = ks * 16;
            wmma::fragment<wmma::matrix_a, 16, 16, 16, __half, wmma::row_major> af[2];
            wmma::fragment<wmma::matrix_b, 16, 16, 16, __half, wmma::row_major> bf[4];
#pragma unroll
            for (int i = 0; i < 2; i++)
                wmma::load_matrix_sync(af[i], As + (warpM * 32 + i * 16) * 136 + k0, 136);
#pragma unroll
            for (int j = 0; j < 4; j++)
                wmma::load_matrix_sync(bf[j], Bs + k0 * 136 + warpN * 64 + j * 16, 136);
#pragma unroll
            for (int i = 0; i < 2; i++)
#pragma unroll
                for (int j = 0; j < 4; j++)
                    wmma::mma_sync(acc[i][j], af[i], bf[j], acc[i][j]);
        }
        __syncthreads();
    }

#pragma unroll
    for (int i = 0; i < 2; i++)
#pragma unroll
        for (int j = 0; j < 4; j++)
            wmma::store_matrix_sync(Cs + (warpM * 32 + i * 16) * 132 + warpN * 64 + j * 16,
                                    acc[i][j], 132, wmma::mem_row_major);
    __syncthreads();

    const float RS = 0.9999950000374997f;  // 1/sqrt(1+1e-5)
    const int r = tid >> 1;
    const int cb0 = (tid & 1) * 64;
    const int grow = rowBase + r;
    if (grow < NN) {
#pragma unroll
        for (int j = 0; j < 8; j++) {
            int c0 = cb0 + j * 8;
            float4 v0 = *(const float4*)(Cs + r * 132 + c0);
            float4 v1 = *(const float4*)(Cs + r * 132 + c0 + 4);
            float t[8] = {v0.x, v0.y, v0.z, v0.w, v1.x, v1.y, v1.z, v1.w};
#pragma unroll
            for (int q = 0; q < 8; q++) {
                int c = c0 + q;
                t[q] += bias[c];
                if (gam) t[q] = fmaxf(t[q] * gam[c] * RS + bet[c], 0.f);
            }
            __half2 h0 = __floats2half2_rn(t[0], t[1]);
            __half2 h1 = __floats2half2_rn(t[2], t[3]);
            __half2 h2 = __floats2half2_rn(t[4], t[5]);
            __half2 h3 = __floats2half2_rn(t[6], t[7]);
            *(uint4*)(out + (size_t)grow * 128 + c0) =
                make_uint4(*(uint32_t*)&h0, *(uint32_t*)&h1, *(uint32_t*)&h2, *(uint32_t*)&h3);
        }
    }
}

// ---------------- SpMM hop, dual order via blockIdx.y ----------------
__global__ __launch_bounds__(256) void spmm_hop(
    const int* __restrict__ rowptrB,
    const int* __restrict__ csrcB,
    const float* __restrict__ cwB,
    const __half* __restrict__ zhB,
    int k)
{
    const int o = blockIdx.y;
    const int* rowptr = rowptrB + (size_t)o * (NN + 1);
    const int* csrc = csrcB + (size_t)o * EE;
    const float* cw = cwB + (size_t)o * EE;
    const __half* zin = zhB + (size_t)o * ZSTRIDE + (size_t)k * NH;
    __half* zout = (__half*)zhB + (size_t)o * ZSTRIDE + (size_t)(k + 1) * NH;

    int warp = (blockIdx.x * blockDim.x + threadIdx.x) >> 5;
    int lane = threadIdx.x & 31;
    if (warp >= NN) return;
    int beg = rowptr[warp], end = rowptr[warp + 1];

    float ax = 0.f, ay = 0.f, az = 0.f, aw = 0.f;
    int e = beg;
    for (; e + 4 <= end; e += 4) {
        int s0 = csrc[e], s1 = csrc[e + 1], s2 = csrc[e + 2], s3 = csrc[e + 3];
        float w0 = cw[e], w1 = cw[e + 1], w2 = cw[e + 2], w3 = cw[e + 3];
        uint2 u0 = *(const uint2*)(zin + (size_t)s0 * 128 + lane * 4);
        uint2 u1 = *(const uint2*)(zin + (size_t)s1 * 128 + lane * 4);
        uint2 u2 = *(const uint2*)(zin + (size_t)s2 * 128 + lane * 4);
        uint2 u3 = *(const uint2*)(zin + (size_t)s3 * 128 + lane * 4);
        float2 a0 = __half22float2(*(__half2*)&u0.x), b0 = __half22float2(*(__half2*)&u0.y);
        float2 a1 = __half22float2(*(__half2*)&u1.x), b1 = __half22float2(*(__half2*)&u1.y);
        float2 a2 = __half22float2(*(__half2*)&u2.x), b2 = __half22float2(*(__half2*)&u2.y);
        float2 a3 = __half22float2(*(__half2*)&u3.x), b3 = __half22float2(*(__half2*)&u3.y);
        ax = fmaf(w0, a0.x, fmaf(w1, a1.x, fmaf(w2, a2.x, fmaf(w3, a3.x, ax))));
        ay = fmaf(w0, a0.y, fmaf(w1, a1.y, fmaf(w2, a2.y, fmaf(w3, a3.y, ay))));
        az = fmaf(w0, b0.x, fmaf(w1, b1.x, fmaf(w2, b2.x, fmaf(w3, b3.x, az))));
        aw = fmaf(w0, b0.y, fmaf(w1, b1.y, fmaf(w2, b2.y, fmaf(w3, b3.y, aw))));
    }
    for (; e < end; ++e) {
        int s = csrc[e];
        float w = cw[e];
        uint2 u = *(const uint2*)(zin + (size_t)s * 128 + lane * 4);
        float2 a = __half22float2(*(__half2*)&u.x), b = __half22float2(*(__half2*)&u.y);
        ax = fmaf(w, a.x, ax); ay = fmaf(w, a.y, ay);
        az = fmaf(w, b.x, az); aw = fmaf(w, b.y, aw);
    }

    __half2 h0 = __floats2half2_rn(ax, ay);
    __half2 h1 = __floats2half2_rn(az, aw);
    *(uint2*)(zout + (size_t)warp * 128 + lane * 4) = make_uint2(*(uint32_t*)&h0, *(uint32_t*)&h1);
}

// ---------------- combine (dual order): xcat[n, o*128+c] = sum_k fW[lo,k]*zh[o,k,n,c] ----------------
__global__ void combine_hid(const __half* __restrict__ zh,
                            const float* __restrict__ fWl,   // fW + l*OO*11
                            __half* __restrict__ xcat)
{
    const int o = blockIdx.y;
    const __half* zo = zh + (size_t)o * ZSTRIDE;
    const float* fw = fWl + (size_t)o * (KHOP + 1);
    int i = blockIdx.x * blockDim.x + threadIdx.x;
    if (i >= (int)(NH / 8)) return;
    float facc[8] = {0, 0, 0, 0, 0, 0, 0, 0};
#pragma unroll
    for (int k = 0; k <= KHOP; k++) {
        float f = fw[k];
        uint4 u = *(const uint4*)(zo + (size_t)k * NH + (size_t)i * 8);
        float2 p0 = __half22float2(*(__half2*)&u.x);
        float2 p1 = __half22float2(*(__half2*)&u.y);
        float2 p2 = __half22float2(*(__half2*)&u.z);
        float2 p3 = __half22float2(*(__half2*)&u.w);
        facc[0] = fmaf(f, p0.x, facc[0]); facc[1] = fmaf(f, p0.y, facc[1]);
        facc[2] = fmaf(f, p1.x, facc[2]); facc[3] = fmaf(f, p1.y, facc[3]);
        facc[4] = fmaf(f, p2.x, facc[4]); facc[5] = fmaf(f, p2.y, facc[5]);
        facc[6] = fmaf(f, p3.x, facc[6]); facc[7] = fmaf(f, p3.y, facc[7]);
    }
    size_t elem = (size_t)i * 8;
    size_t row = elem >> 7;
    int col = (int)(elem & 127);
    __half2 h0 = __floats2half2_rn(facc[0], facc[1]);
    __half2 h1 = __floats2half2_rn(facc[2], facc[3]);
    __half2 h2 = __floats2half2_rn(facc[4], facc[5]);
    __half2 h3 = __floats2half2_rn(facc[6], facc[7]);
    *(uint4*)(xcat + row * 256 + (size_t)o * 128 + col) =
        make_uint4(*(uint32_t*)&h0, *(uint32_t*)&h1, *(uint32_t*)&h2, *(uint32_t*)&h3);
}

// ---------------- pooling + head ----------------
__global__ void pool_kernel(const __half* __restrict__ h, const int* __restrict__ batch,
                            float* __restrict__ p) {
    int idx = blockIdx.x * blockDim.x + threadIdx.x;
    if (idx >= NN * HH) return;
    int node = idx >> 7;
    int f = idx & 127;
    atomicAdd(&p[batch[node] * HH + f], __half2float(h[idx]));
}

__global__ void head1(const float* __restrict__ p, const float* __restrict__ W1,
                      const float* __restrict__ b1, float* __restrict__ p1) {
    int i = blockIdx.x * blockDim.x + threadIdx.x;
    if (i >= GG * HH) return;
    int g = i >> 7, j = i & 127;
    float acc = b1[j];
    for (int k = 0; k < HH; k++)
        acc = fmaf(p[g * HH + k], W1[k * HH + j], acc);
    p1[i] = fmaxf(acc, 0.f);
}

__global__ void head2(const float* __restrict__ p1, const float* __restrict__ W2,
                      const float* __restrict__ b2, float* __restrict__ outp) {
    int i = blockIdx.x * blockDim.x + threadIdx.x;
    if (i >= GG * CC) return;
    int g = i / CC, j = i % CC;
    float acc = b2[j];
    for (int k = 0; k < HH; k++)
        acc = fmaf(p1[g * HH + k], W2[k * CC + j], acc);
    outp[i] = acc;
}

// ---------------- host orchestration ----------------
extern "C" void kernel_launch(void* const* d_in, const int* in_sizes, int n_in,
                              void* d_out, int out_size) {
    const float* x      = (const float*)d_in[0];
    const int*   eidx   = (const int*)  d_in[1];
    const float* ew     = (const float*)d_in[2];
    const int*   batch  = (const int*)  d_in[3];
    const float* W_in   = (const float*)d_in[4];
    const float* b_in   = (const float*)d_in[5];
    const float* fW     = (const float*)d_in[6];
    const float* W_out  = (const float*)d_in[7];
    const float* b_out  = (const float*)d_in[8];
    const float* Wn1    = (const float*)d_in[9];
    const float* bn1    = (const float*)d_in[10];
    const float* g1     = (const float*)d_in[11];
    const float* be1    = (const float*)d_in[12];
    const float* Wn2    = (const float*)d_in[13];
    const float* bn2    = (const float*)d_in[14];
    const float* g2     = (const float*)d_in[15];
    const float* be2    = (const float*)d_in[16];
    const float* W1     = (const float*)d_in[17];
    const float* b1     = (const float*)d_in[18];
    const float* W2     = (const float*)d_in[19];
    const float* b2     = (const float*)d_in[20];
    float* outp = (float*)d_out;

    __half *x16, *zh, *xcat16, *t16, *h16, *win16, *wfold16, *wn216;
    float *bfold, *pool, *p1, *cw;
    int *rowptr, *cursor, *csrc;
    cudaGetSymbolAddress((void**)&x16, g_x16);
    cudaGetSymbolAddress((void**)&zh, g_zh);
    cudaGetSymbolAddress((void**)&xcat16, g_xcat16);
    cudaGetSymbolAddress((void**)&t16, g_t16);
    cudaGetSymbolAddress((void**)&h16, g_h16);
    cudaGetSymbolAddress((void**)&win16, g_win16);
    cudaGetSymbolAddress((void**)&wfold16, g_wfold16);
    cudaGetSymbolAddress((void**)&bfold, g_bfold);
    cudaGetSymbolAddress((void**)&wn216, g_wn216);
    cudaGetSymbolAddress((void**)&pool, g_pool);
    cudaGetSymbolAddress((void**)&p1, g_p1);
    cudaGetSymbolAddress((void**)&rowptr, g_rowptr);
    cudaGetSymbolAddress((void**)&cursor, g_cursor);
    cudaGetSymbolAddress((void**)&csrc, g_csrc);
    cudaGetSymbolAddress((void**)&cw, g_cw);

    const size_t WIN_SZ = (size_t)LL * OO * HH * HH;
    const size_t WN_SZ  = (size_t)LL * HH * HH;
    const int EB = (EE + 255) / 256;
    const int MB = (NN + 127) / 128;
    const int SB = ((NN * 32) + 255) / 256;
    const int CB = ((int)(NH / 8) + 255) / 256;
    const int GEMM_SMEM = 128 * 136 * 2 * 2;

    cudaFuncSetAttribute(gemm16, cudaFuncAttributeMaxDynamicSharedMemorySize, GEMM_SMEM);

    // ---- weight prep ----
    cast_f2h<<<(int)((WIN_SZ / 4 + 255) / 256), 256>>>(W_in, win16, (int)WIN_SZ);
    cast_f2h<<<(int)((WN_SZ / 4 + 255) / 256), 256>>>(Wn2, wn216, (int)WN_SZ);
    cast_f2h<<<(int)((NH / 4 + 255) / 256), 256>>>(x, x16, (int)NH);
    {
        dim3 g((256 * 128 + 255) / 256, LL);
        fold_w<<<g, 256>>>(W_out, Wn1, wfold16);
        dim3 gb(1, LL);
        fold_b<<<gb, 128>>>(b_out, Wn1, bn1, bfold);
    }

    // ---- build CSR per order ----
    for (int o = 0; o < OO; o++) {
        const int* dst = eidx + (size_t)o * 2 * EE;
        const int* src = dst + EE;
        int* cnt = cursor + (size_t)o * NN;
        int* rp  = rowptr + (size_t)o * (NN + 1);
        cudaMemsetAsync(cnt, 0, NN * sizeof(int), 0);
        csr_count<<<EB, 256>>>(dst, cnt);
        csr_scan<<<1, 1024>>>(cnt, rp);
        cudaMemcpyAsync(cnt, rp, NN * sizeof(int), cudaMemcpyDeviceToDevice, 0);
        csr_fill<<<EB, 256>>>(dst, src, ew + (size_t)o * EE, cnt,
                              csrc + (size_t)o * EE, cw + (size_t)o * EE);
    }

    const __half* hin = x16;
    for (int l = 0; l < LL; l++) {
        // z0 for both orders: zh[o][0] = hin @ Win[l,o] + b_in[l,o]
        {
            dim3 g(MB, OO);
            gemm16<<<g, 256, GEMM_SMEM>>>(hin, 128, 128,
                                          win16 + (size_t)l * OO * HH * HH, (size_t)HH * HH,
                                          b_in + (size_t)l * OO * HH, HH,
                                          zh, ZSTRIDE,
                                          nullptr, nullptr);
        }
        // 10 hops, both orders per launch
        for (int k = 0; k < KHOP; k++) {
            dim3 g(SB, OO);
            spmm_hop<<<g, 256>>>(rowptr, csrc, cw, zh, k);
        }
        // combine both orders -> xcat16
        {
            dim3 g(CB, OO);
            combine_hid<<<g, 256>>>(zh, fW + (size_t)l * OO * (KHOP + 1), xcat16);
        }
        // t = relu(bn1(xcat @ Wfold + bfold))   [K=256]
        gemm16<<<dim3(MB, 1), 256, GEMM_SMEM>>>(xcat16, 256, 256,
                                      wfold16 + (size_t)l * 256 * HH, 0,
                                      bfold + (size_t)l * HH, 0,
                                      t16, 0,
                                      g1 + (size_t)l * HH, be1 + (size_t)l * HH);
        // h = relu(bn2(t @ Wn2 + bn2))
        gemm16<<<dim3(MB, 1), 256, GEMM_SMEM>>>(t16, 128, 128,
                                      wn216 + (size_t)l * HH * HH, 0,
                                      bn2 + (size_t)l * HH, 0,
                                      h16, 0,
                                      g2 + (size_t)l * HH, be2 + (size_t)l * HH);
        hin = h16;
    }

    cudaMemsetAsync(pool, 0, GG * HH * sizeof(float), 0);
    pool_kernel<<<(NN * HH + 255) / 256, 256>>>(h16, batch, pool);
    head1<<<(GG * HH + 255) / 256, 256>>>(pool, W1, b1, p1);
    head2<<<(GG * CC + 255) / 256, 256>>>(p1, W2, b2, outp);
}